// round 3
// baseline (speedup 1.0000x reference)
#include <cuda_runtime.h>
#include <cstdint>

#define NN 50000
#define BB 512
#define DD 32
#define NSAMP 1001
#define BTILE 16

// Scratch (no cudaMalloc allowed)
__device__ float4 g_nodeDots[NN];               // (u0, u1, v0, v1) per node
__device__ float  g_cSrc[BB], g_cDst[BB];
__device__ float  g_psiB[BB], g_kB[BB];
__device__ int    g_etB[BB];
__device__ float  g_gBase[BB], g_alphaB[BB], g_wtB[BB];

// ---------------------------------------------------------------------------
// Kernel A: per-node dot products with the 4 weight half-rows, plus per-batch
// scalar constants (everything that doesn't vary with n).
// ---------------------------------------------------------------------------
__global__ void precompute_kernel(
    const float* __restrict__ emb, const int* __restrict__ assoc,
    const int* __restrict__ src, const int* __restrict__ pos_dst,
    const float* __restrict__ last_update, const float* __restrict__ cur_time,
    const int* __restrict__ et, const float* __restrict__ W,
    const float* __restrict__ bvec, const float* __restrict__ psi,
    const float* __restrict__ alpha, const float* __restrict__ w_t,
    int nodeBlocks)
{
    __shared__ float sW[128];  // W is (2, 64) row-major
    int tid = threadIdx.x;
    if (tid < 128) sW[tid] = W[tid];
    __syncthreads();

    if ((int)blockIdx.x < nodeBlocks) {
        int n = blockIdx.x * 256 + tid;
        if (n < NN) {
            const float4* row = (const float4*)(emb + (size_t)n * DD);
            float u0 = 0.f, u1 = 0.f, v0 = 0.f, v1 = 0.f;
            #pragma unroll
            for (int i = 0; i < 8; i++) {
                float4 e4 = row[i];
                const float* wu0 = sW +       i * 4;   // W[0][0:32]
                const float* wu1 = sW + 64  + i * 4;   // W[1][0:32]
                const float* wv0 = sW + 32  + i * 4;   // W[0][32:64]
                const float* wv1 = sW + 96  + i * 4;   // W[1][32:64]
                u0 += e4.x * wu0[0] + e4.y * wu0[1] + e4.z * wu0[2] + e4.w * wu0[3];
                u1 += e4.x * wu1[0] + e4.y * wu1[1] + e4.z * wu1[2] + e4.w * wu1[3];
                v0 += e4.x * wv0[0] + e4.y * wv0[1] + e4.z * wv0[2] + e4.w * wv0[3];
                v1 += e4.x * wv1[0] + e4.y * wv1[1] + e4.z * wv1[2] + e4.w * wv1[3];
            }
            g_nodeDots[n] = make_float4(u0, u1, v0, v1);
        }
    } else {
        int idx = (blockIdx.x - nodeBlocks) * 256 + tid;
        if (idx < BB) {
            int e = (et[idx] > 0) ? 1 : 0;
            int s = assoc[src[idx]];
            int d = assoc[pos_dst[idx]];
            float ct = cur_time[idx];
            float tds = (ct - last_update[s]) * (1.0f / 100.0f);   // td / TRAIN_TD_MAX
            float tdd = (ct - last_update[d]) * (1.0f / 100.0f);
            const float* Wu = sW + e * 64;
            const float* Wv = sW + e * 64 + 32;
            const float* zs = emb + (size_t)s * DD;
            const float* zd = emb + (size_t)d * DD;
            float dus = 0.f, dvd = 0.f;
            #pragma unroll
            for (int i = 0; i < DD; i++) {
                dus += zs[i] * Wu[i];
                dvd += zd[i] * Wv[i];
            }
            float be = bvec[e], al = alpha[e], wt = w_t[e], ps = psi[e];
            g_cSrc[idx]   = dus + be + al * expf(-wt * tds);
            g_cDst[idx]   = dvd + be + al * expf(-wt * tdd);
            g_gBase[idx]  = dus + dvd + be;
            g_psiB[idx]   = ps;
            g_kB[idx]     = 1.0f / (ps + 1e-7f);
            g_etB[idx]    = e;
            g_alphaB[idx] = al;
            g_wtB[idx]    = wt;
        }
    }
}

// Stable hawkes output: psi * (max(gp,0) + log(1 + exp(-|gp|)))
__device__ __forceinline__ float hawkes_f(float g, float k, float ps) {
    float gp = g * k;
    float e  = __expf(-fabsf(gp));
    float l  = __logf(1.0f + e);
    return ps * (fmaxf(gp, 0.0f) + l);
}

// ---------------------------------------------------------------------------
// Kernel B: the 2 x (512, 50000) lambda arrays. Each thread owns 4 consecutive
// nodes (one 64B node-dot read) and reuses them across BTILE=16 batch rows,
// writing float4 per array per row.
// ---------------------------------------------------------------------------
__global__ void __launch_bounds__(256) lambda_kernel(float* __restrict__ out)
{
    __shared__ float sc_src[BTILE], sc_dst[BTILE], s_psi[BTILE], s_k[BTILE];
    __shared__ int   s_et[BTILE];

    int tid = threadIdx.x;
    int b0  = blockIdx.y * BTILE;
    if (tid < BTILE) {
        int b = b0 + tid;
        sc_src[tid] = g_cSrc[b];
        sc_dst[tid] = g_cDst[b];
        s_psi[tid]  = g_psiB[b];
        s_k[tid]    = g_kB[b];
        s_et[tid]   = g_etB[b];
    }
    __syncthreads();

    int n4 = blockIdx.x * 256 + tid;
    if (n4 >= NN / 4) return;

    float4 d0 = g_nodeDots[n4 * 4 + 0];
    float4 d1 = g_nodeDots[n4 * 4 + 1];
    float4 d2 = g_nodeDots[n4 * 4 + 2];
    float4 d3 = g_nodeDots[n4 * 4 + 3];

    const size_t dstOff = (size_t)BB * NN;
    const size_t nbase  = (size_t)n4 * 4;

    #pragma unroll 4
    for (int j = 0; j < BTILE; j++) {
        int b = b0 + j;
        float cs = sc_src[j], cd = sc_dst[j];
        float ps = s_psi[j], k = s_k[j];
        bool  e  = (s_et[j] != 0);

        // src-lambda uses per-node V dots; dst-lambda uses per-node U dots
        float v0 = e ? d0.w : d0.z, u0 = e ? d0.y : d0.x;
        float v1 = e ? d1.w : d1.z, u1 = e ? d1.y : d1.x;
        float v2 = e ? d2.w : d2.z, u2 = e ? d2.y : d2.x;
        float v3 = e ? d3.w : d3.z, u3 = e ? d3.y : d3.x;

        float4 rs, rd;
        rs.x = hawkes_f(cs + v0, k, ps);
        rs.y = hawkes_f(cs + v1, k, ps);
        rs.z = hawkes_f(cs + v2, k, ps);
        rs.w = hawkes_f(cs + v3, k, ps);
        rd.x = hawkes_f(cd + u0, k, ps);
        rd.y = hawkes_f(cd + u1, k, ps);
        rd.z = hawkes_f(cd + u2, k, ps);
        rd.w = hawkes_f(cd + u3, k, ps);

        size_t base = (size_t)b * NN + nbase;
        *(float4*)(out + base)          = rs;
        *(float4*)(out + dstOff + base) = rd;
    }
}

// ---------------------------------------------------------------------------
// Kernel C: return_time_pred — per-b cumsum over 1001 samples via block scan,
// then trapezoid: 0.01 * (sum(ts) - 0.5*ts[last])  (ts[0] == 0).
// ---------------------------------------------------------------------------
__global__ void __launch_bounds__(256) rtp_kernel(float* __restrict__ out)
{
    int b    = blockIdx.x;
    int tid  = threadIdx.x;
    int lane = tid & 31;
    int wid  = tid >> 5;

    __shared__ float warpSums[8];
    __shared__ float sLast;

    float gb = g_gBase[b], al = g_alphaB[b], wt = g_wtB[b];
    float ps = g_psiB[b],  k  = g_kB[b];

    float carry = 0.0f;  // running integral before this chunk
    float acc   = 0.0f;  // sum of t_sample

    for (int c = 0; c < 4; c++) {
        int   s  = c * 256 + tid;
        float td = (float)s * 0.01f;
        float x = 0.0f, inten = 0.0f;
        if (s < NSAMP) {
            float g  = gb + al * __expf(-wt * (td * (1.0f / 100.0f)));
            float gp = g * k;
            inten = ps * (fmaxf(gp, 0.0f) + __logf(1.0f + __expf(-fabsf(gp))));
            x = 0.01f * inten;  // TIMESTEP * intensity
        }

        // inclusive block scan of x
        float v = x;
        #pragma unroll
        for (int off = 1; off < 32; off <<= 1) {
            float t = __shfl_up_sync(0xffffffffu, v, off);
            if (lane >= off) v += t;
        }
        if (lane == 31) warpSums[wid] = v;
        __syncthreads();
        if (tid < 8) {
            float wv = warpSums[tid];
            #pragma unroll
            for (int off = 1; off < 8; off <<= 1) {
                float t = __shfl_up_sync(0xffu, wv, off);
                if (tid >= off) wv += t;
            }
            warpSums[tid] = wv;
        }
        __syncthreads();
        float incl     = v + (wid ? warpSums[wid - 1] : 0.0f);
        float chunkSum = warpSums[7];

        if (s < NSAMP) {
            float integral = carry + incl;
            float density  = inten * __expf(-integral);
            float ts       = td * density;
            acc += ts;
            if (s == NSAMP - 1) sLast = ts;
        }
        carry += chunkSum;
        __syncthreads();
    }

    // block reduce acc
    #pragma unroll
    for (int off = 16; off; off >>= 1)
        acc += __shfl_down_sync(0xffffffffu, acc, off);
    if (lane == 0) warpSums[wid] = acc;
    __syncthreads();
    if (tid == 0) {
        float tot = 0.0f;
        #pragma unroll
        for (int i = 0; i < 8; i++) tot += warpSums[i];
        out[(size_t)2 * BB * NN + b] = 0.01f * (tot - 0.5f * sLast);
    }
}

// ---------------------------------------------------------------------------
extern "C" void kernel_launch(void* const* d_in, const int* in_sizes, int n_in,
                              void* d_out, int out_size)
{
    const float* emb         = (const float*)d_in[0];
    const int*   assoc       = (const int*)  d_in[1];
    const int*   src         = (const int*)  d_in[2];
    const int*   pos_dst     = (const int*)  d_in[3];
    // d_in[4] = neg_dst (unused by reference)
    const float* last_update = (const float*)d_in[5];
    const float* cur_time    = (const float*)d_in[6];
    const int*   et          = (const int*)  d_in[7];
    const float* W           = (const float*)d_in[8];
    const float* bvec        = (const float*)d_in[9];
    const float* psi         = (const float*)d_in[10];
    const float* alpha       = (const float*)d_in[11];
    const float* w_t         = (const float*)d_in[12];

    float* out = (float*)d_out;

    int nodeBlocks = (NN + 255) / 256;         // 196
    int bBlocks    = (BB + 255) / 256;         // 2
    precompute_kernel<<<nodeBlocks + bBlocks, 256>>>(
        emb, assoc, src, pos_dst, last_update, cur_time, et,
        W, bvec, psi, alpha, w_t, nodeBlocks);

    dim3 grid((NN / 4 + 255) / 256, BB / BTILE);  // (49, 32)
    lambda_kernel<<<grid, 256>>>(out);

    rtp_kernel<<<BB, 256>>>(out);
}

// round 4
// speedup vs baseline: 1.3017x; 1.3017x over previous
#include <cuda_runtime.h>
#include <cstdint>

#define NN 50000
#define BB 512
#define DD 32
#define NSAMP 1001
#define BTILE 16

// Scratch (no cudaMalloc allowed)
__device__ float4 g_nodeDots[NN];               // (u0, u1, v0, v1) per node
__device__ float  g_cSrc[BB], g_cDst[BB];
__device__ float  g_psiB[BB], g_kB[BB];
__device__ int    g_etB[BB];
__device__ float  g_gBase[BB], g_alphaB[BB], g_wtB[BB];

// ---------------------------------------------------------------------------
// Kernel A: node dots (4 lanes per node for latency hiding) + per-batch
// constants (8 lanes per batch item).
// ---------------------------------------------------------------------------
__global__ void __launch_bounds__(256) precompute_kernel(
    const float* __restrict__ emb, const int* __restrict__ assoc,
    const int* __restrict__ src, const int* __restrict__ pos_dst,
    const float* __restrict__ last_update, const float* __restrict__ cur_time,
    const int* __restrict__ et, const float* __restrict__ W,
    const float* __restrict__ bvec, const float* __restrict__ psi,
    const float* __restrict__ alpha, const float* __restrict__ w_t,
    int nodeBlocks)
{
    __shared__ float sW[128];  // W is (2, 64) row-major
    int tid = threadIdx.x;
    if (tid < 128) sW[tid] = W[tid];
    __syncthreads();

    if ((int)blockIdx.x < nodeBlocks) {
        // 4 lanes per node: lane q reads elements [8q, 8q+8)
        int g = blockIdx.x * 256 + tid;
        if (g >= NN * 4) return;
        int n = g >> 2;
        int q = g & 3;

        const float4* row = (const float4*)(emb + (size_t)n * DD) + q * 2;
        float4 a = row[0];
        float4 c = row[1];

        const float* wu0 = sW +       q * 8;   // W[0][0:32]
        const float* wv0 = sW + 32  + q * 8;   // W[0][32:64]
        const float* wu1 = sW + 64  + q * 8;   // W[1][0:32]
        const float* wv1 = sW + 96  + q * 8;   // W[1][32:64]

        float u0 = a.x*wu0[0] + a.y*wu0[1] + a.z*wu0[2] + a.w*wu0[3]
                 + c.x*wu0[4] + c.y*wu0[5] + c.z*wu0[6] + c.w*wu0[7];
        float u1 = a.x*wu1[0] + a.y*wu1[1] + a.z*wu1[2] + a.w*wu1[3]
                 + c.x*wu1[4] + c.y*wu1[5] + c.z*wu1[6] + c.w*wu1[7];
        float v0 = a.x*wv0[0] + a.y*wv0[1] + a.z*wv0[2] + a.w*wv0[3]
                 + c.x*wv0[4] + c.y*wv0[5] + c.z*wv0[6] + c.w*wv0[7];
        float v1 = a.x*wv1[0] + a.y*wv1[1] + a.z*wv1[2] + a.w*wv1[3]
                 + c.x*wv1[4] + c.y*wv1[5] + c.z*wv1[6] + c.w*wv1[7];

        // reduce across the 4-lane group
        #pragma unroll
        for (int off = 1; off <= 2; off <<= 1) {
            u0 += __shfl_xor_sync(0xffffffffu, u0, off);
            u1 += __shfl_xor_sync(0xffffffffu, u1, off);
            v0 += __shfl_xor_sync(0xffffffffu, v0, off);
            v1 += __shfl_xor_sync(0xffffffffu, v1, off);
        }
        float outv = (q == 0) ? u0 : (q == 1) ? u1 : (q == 2) ? v0 : v1;
        ((float*)g_nodeDots)[g] = outv;   // coalesced: component q of node n
    } else {
        // 8 lanes per batch item: 32 items per block
        int idx = (blockIdx.x - nodeBlocks) * 32 + (tid >> 3);
        int r   = tid & 7;
        if (idx >= BB) return;

        int e = (et[idx] > 0) ? 1 : 0;
        int s = assoc[src[idx]];
        int d = assoc[pos_dst[idx]];

        float4 zs4 = *(const float4*)(emb + (size_t)s * DD + r * 4);
        float4 zd4 = *(const float4*)(emb + (size_t)d * DD + r * 4);

        const float* Wu = sW + e * 64 + r * 4;
        const float* Wv = sW + e * 64 + 32 + r * 4;
        float dus = zs4.x*Wu[0] + zs4.y*Wu[1] + zs4.z*Wu[2] + zs4.w*Wu[3];
        float dvd = zd4.x*Wv[0] + zd4.y*Wv[1] + zd4.z*Wv[2] + zd4.w*Wv[3];

        #pragma unroll
        for (int off = 1; off <= 4; off <<= 1) {
            dus += __shfl_xor_sync(0xffffffffu, dus, off);
            dvd += __shfl_xor_sync(0xffffffffu, dvd, off);
        }

        if (r == 0) {
            float ct  = cur_time[idx];
            float tds = (ct - last_update[s]) * (1.0f / 100.0f);
            float tdd = (ct - last_update[d]) * (1.0f / 100.0f);
            float be = bvec[e], al = alpha[e], wt = w_t[e], ps = psi[e];
            g_cSrc[idx]   = dus + be + al * expf(-wt * tds);
            g_cDst[idx]   = dvd + be + al * expf(-wt * tdd);
            g_gBase[idx]  = dus + dvd + be;
            g_psiB[idx]   = ps;
            g_kB[idx]     = 1.0f / (ps + 1e-7f);
            g_etB[idx]    = e;
            g_alphaB[idx] = al;
            g_wtB[idx]    = wt;
        }
    }
}

// Stable hawkes output: psi * (max(gp,0) + log(1 + exp(-|gp|)))
__device__ __forceinline__ float hawkes_f(float g, float k, float ps) {
    float gp = g * k;
    float e  = __expf(-fabsf(gp));
    float l  = __logf(1.0f + e);
    return ps * (fmaxf(gp, 0.0f) + l);
}

// ---------------------------------------------------------------------------
// Kernel B: the 2 x (512, 50000) lambda arrays. Each thread owns 4 consecutive
// nodes (one 64B node-dot read) and reuses them across BTILE=16 batch rows,
// writing one streaming float4 per array per row.
// ---------------------------------------------------------------------------
__global__ void __launch_bounds__(256) lambda_kernel(float* __restrict__ out)
{
    __shared__ float sc_src[BTILE], sc_dst[BTILE], s_psi[BTILE], s_k[BTILE];
    __shared__ int   s_et[BTILE];

    int tid = threadIdx.x;
    int b0  = blockIdx.y * BTILE;
    if (tid < BTILE) {
        int b = b0 + tid;
        sc_src[tid] = g_cSrc[b];
        sc_dst[tid] = g_cDst[b];
        s_psi[tid]  = g_psiB[b];
        s_k[tid]    = g_kB[b];
        s_et[tid]   = g_etB[b];
    }
    __syncthreads();

    int n4 = blockIdx.x * 256 + tid;
    if (n4 >= NN / 4) return;

    float4 d0 = g_nodeDots[n4 * 4 + 0];
    float4 d1 = g_nodeDots[n4 * 4 + 1];
    float4 d2 = g_nodeDots[n4 * 4 + 2];
    float4 d3 = g_nodeDots[n4 * 4 + 3];

    const size_t dstOff = (size_t)BB * NN;
    const size_t nbase  = (size_t)n4 * 4;

    #pragma unroll 4
    for (int j = 0; j < BTILE; j++) {
        int b = b0 + j;
        float cs = sc_src[j], cd = sc_dst[j];
        float ps = s_psi[j], k = s_k[j];
        bool  e  = (s_et[j] != 0);

        // src-lambda uses per-node V dots; dst-lambda uses per-node U dots
        float v0 = e ? d0.w : d0.z, u0 = e ? d0.y : d0.x;
        float v1 = e ? d1.w : d1.z, u1 = e ? d1.y : d1.x;
        float v2 = e ? d2.w : d2.z, u2 = e ? d2.y : d2.x;
        float v3 = e ? d3.w : d3.z, u3 = e ? d3.y : d3.x;

        float4 rs, rd;
        rs.x = hawkes_f(cs + v0, k, ps);
        rs.y = hawkes_f(cs + v1, k, ps);
        rs.z = hawkes_f(cs + v2, k, ps);
        rs.w = hawkes_f(cs + v3, k, ps);
        rd.x = hawkes_f(cd + u0, k, ps);
        rd.y = hawkes_f(cd + u1, k, ps);
        rd.z = hawkes_f(cd + u2, k, ps);
        rd.w = hawkes_f(cd + u3, k, ps);

        size_t base = (size_t)b * NN + nbase;
        __stcs((float4*)(out + base), rs);
        __stcs((float4*)(out + dstOff + base), rd);
    }
}

// ---------------------------------------------------------------------------
// Kernel C: return_time_pred — per-b cumsum over 1001 samples via block scan,
// then trapezoid: 0.01 * (sum(ts) - 0.5*ts[last])  (ts[0] == 0).
// ---------------------------------------------------------------------------
__global__ void __launch_bounds__(256) rtp_kernel(float* __restrict__ out)
{
    int b    = blockIdx.x;
    int tid  = threadIdx.x;
    int lane = tid & 31;
    int wid  = tid >> 5;

    __shared__ float warpSums[8];
    __shared__ float sLast;

    float gb = g_gBase[b], al = g_alphaB[b], wt = g_wtB[b];
    float ps = g_psiB[b],  k  = g_kB[b];

    float carry = 0.0f;  // running integral before this chunk
    float acc   = 0.0f;  // sum of t_sample

    for (int c = 0; c < 4; c++) {
        int   s  = c * 256 + tid;
        float td = (float)s * 0.01f;
        float x = 0.0f, inten = 0.0f;
        if (s < NSAMP) {
            float g  = gb + al * __expf(-wt * (td * (1.0f / 100.0f)));
            float gp = g * k;
            inten = ps * (fmaxf(gp, 0.0f) + __logf(1.0f + __expf(-fabsf(gp))));
            x = 0.01f * inten;  // TIMESTEP * intensity
        }

        // inclusive block scan of x
        float v = x;
        #pragma unroll
        for (int off = 1; off < 32; off <<= 1) {
            float t = __shfl_up_sync(0xffffffffu, v, off);
            if (lane >= off) v += t;
        }
        if (lane == 31) warpSums[wid] = v;
        __syncthreads();
        if (tid < 8) {
            float wv = warpSums[tid];
            #pragma unroll
            for (int off = 1; off < 8; off <<= 1) {
                float t = __shfl_up_sync(0xffu, wv, off);
                if (tid >= off) wv += t;
            }
            warpSums[tid] = wv;
        }
        __syncthreads();
        float incl     = v + (wid ? warpSums[wid - 1] : 0.0f);
        float chunkSum = warpSums[7];

        if (s < NSAMP) {
            float integral = carry + incl;
            float density  = inten * __expf(-integral);
            float ts       = td * density;
            acc += ts;
            if (s == NSAMP - 1) sLast = ts;
        }
        carry += chunkSum;
        __syncthreads();
    }

    // block reduce acc
    #pragma unroll
    for (int off = 16; off; off >>= 1)
        acc += __shfl_down_sync(0xffffffffu, acc, off);
    if (lane == 0) warpSums[wid] = acc;
    __syncthreads();
    if (tid == 0) {
        float tot = 0.0f;
        #pragma unroll
        for (int i = 0; i < 8; i++) tot += warpSums[i];
        out[(size_t)2 * BB * NN + b] = 0.01f * (tot - 0.5f * sLast);
    }
}

// ---------------------------------------------------------------------------
extern "C" void kernel_launch(void* const* d_in, const int* in_sizes, int n_in,
                              void* d_out, int out_size)
{
    const float* emb         = (const float*)d_in[0];
    const int*   assoc       = (const int*)  d_in[1];
    const int*   src         = (const int*)  d_in[2];
    const int*   pos_dst     = (const int*)  d_in[3];
    // d_in[4] = neg_dst (unused by reference)
    const float* last_update = (const float*)d_in[5];
    const float* cur_time    = (const float*)d_in[6];
    const int*   et          = (const int*)  d_in[7];
    const float* W           = (const float*)d_in[8];
    const float* bvec        = (const float*)d_in[9];
    const float* psi         = (const float*)d_in[10];
    const float* alpha       = (const float*)d_in[11];
    const float* w_t         = (const float*)d_in[12];

    float* out = (float*)d_out;

    int nodeBlocks = (NN * 4 + 255) / 256;     // 782 (4 lanes per node)
    int bBlocks    = (BB + 31) / 32;           // 16 (8 lanes per item, 32/block)
    precompute_kernel<<<nodeBlocks + bBlocks, 256>>>(
        emb, assoc, src, pos_dst, last_update, cur_time, et,
        W, bvec, psi, alpha, w_t, nodeBlocks);

    dim3 grid((NN / 4 + 255) / 256, BB / BTILE);  // (49, 32)
    lambda_kernel<<<grid, 256>>>(out);

    rtp_kernel<<<BB, 256>>>(out);
}